// round 1
// baseline (speedup 1.0000x reference)
#include <cuda_runtime.h>
#include <cuda_bf16.h>
#include <math.h>

#define S_LEN 1024
#define CS 384
#define CZ 128
#define CH 256
#define NH 8
#define HD 32
#define PV 8
#define QKVP_N 832   // 256+256+256+64
#define INFV 100000.0f

// ---------------- scratch (__device__ globals, no allocation) ----------------
__device__ __align__(16) float g_sn[S_LEN * CS];
__device__ __align__(16) float g_qkvp[S_LEN * QKVP_N];
__device__ __align__(16) float g_scores[NH * S_LEN * S_LEN];   // qk, then attn in-place
__device__ __align__(16) float g_ao[S_LEN * CH];
__device__ __align__(16) float g_Wall[QKVP_N * CS];
__device__ __align__(16) float g_bias832[QKVP_N];
__device__ __align__(16) float g_gw[NH * CZ];
__device__ float g_gwsum[NH];
__device__ float g_bw[NH];
__device__ __align__(16) float g_coords[S_LEN * 4];
__device__ __align__(16) float g_vp[S_LEN * 24];
__device__ __align__(16) float g_attpts[S_LEN * 24];

// ---------------- prep kernels ----------------
__global__ void pack_w_kernel(const float* __restrict__ Wq, const float* __restrict__ Wk,
                              const float* __restrict__ Wv, const float* __restrict__ Wvp,
                              const float* __restrict__ bvp) {
    int idx = blockIdx.x * blockDim.x + threadIdx.x;
    int total = QKVP_N * CS;
    for (; idx < total; idx += gridDim.x * blockDim.x) {
        int r = idx / CS, c = idx % CS;
        float v;
        if (r < 256)      v = Wq[r * CS + c];
        else if (r < 512) v = Wk[(r - 256) * CS + c];
        else if (r < 768) v = Wv[(r - 512) * CS + c];
        else              v = Wvp[(r - 768) * CS + c];
        g_Wall[idx] = v;
    }
    int t = blockIdx.x * blockDim.x + threadIdx.x;
    if (t < QKVP_N) g_bias832[t] = (t >= 768) ? bvp[t - 768] : 0.0f;
}

__global__ void prep_pair_kernel(const float* __restrict__ ln_z_g,
                                 const float* __restrict__ ln_z_b,
                                 const float* __restrict__ W_pair) {
    __shared__ float red[CZ];
    int c = threadIdx.x;  // 128
    for (int h = 0; h < NH; h++) {
        float w = W_pair[h * CZ + c];
        float gv = ln_z_g[c] * w;
        g_gw[h * CZ + c] = gv;
        red[c] = gv; __syncthreads();
        for (int s = 64; s > 0; s >>= 1) { if (c < s) red[c] += red[c + s]; __syncthreads(); }
        if (c == 0) g_gwsum[h] = red[0];
        __syncthreads();
        red[c] = ln_z_b[c] * w; __syncthreads();
        for (int s = 64; s > 0; s >>= 1) { if (c < s) red[c] += red[c + s]; __syncthreads(); }
        if (c == 0) g_bw[h] = red[0];
        __syncthreads();
    }
}

__global__ void coords_kernel(const float* __restrict__ rigids) {
    int i = blockIdx.x * blockDim.x + threadIdx.x;
    if (i < S_LEN) {
        const float* rg = rigids + i * 16;
        float4 c;
        c.x = rg[3]; c.y = rg[7]; c.z = rg[11]; c.w = 0.0f;
        ((float4*)g_coords)[i] = c;
    }
}

__global__ void ln_s_kernel(const float* __restrict__ s, const float* __restrict__ g,
                            const float* __restrict__ b) {
    int i = blockIdx.x;
    const float* row = s + (long)i * CS;
    __shared__ float red[128];
    int t = threadIdx.x;  // 128
    float x0 = row[t], x1 = row[t + 128], x2 = row[t + 256];
    red[t] = x0 + x1 + x2; __syncthreads();
    for (int st = 64; st > 0; st >>= 1) { if (t < st) red[t] += red[t + st]; __syncthreads(); }
    float mean = red[0] * (1.0f / CS);
    __syncthreads();
    float d0 = x0 - mean, d1 = x1 - mean, d2 = x2 - mean;
    red[t] = d0 * d0 + d1 * d1 + d2 * d2; __syncthreads();
    for (int st = 64; st > 0; st >>= 1) { if (t < st) red[t] += red[t + st]; __syncthreads(); }
    float r = rsqrtf(red[0] * (1.0f / CS) + 1e-5f);
    float* o = g_sn + (long)i * CS;
    o[t]       = d0 * r * g[t]       + b[t];
    o[t + 128] = d1 * r * g[t + 128] + b[t + 128];
    o[t + 256] = d2 * r * g[t + 256] + b[t + 256];
}

// ---------------- generic tiled GEMMs ----------------
#define BM 64
#define BN 64
#define BK 16

// C[m][n] (+)= alpha * ( sum_k A[m][k]*B[n][k] + bias[n] )
__global__ void gemm_nt(const float* __restrict__ A, int lda, long sA,
                        const float* __restrict__ B, int ldb, long sB,
                        float* __restrict__ C, int ldc, long sC,
                        int M, int N, int K,
                        float alpha_const, const float* alpha_ptr,
                        const float* __restrict__ bias, int accumulate) {
    A += (long)blockIdx.z * sA;
    B += (long)blockIdx.z * sB;
    C += (long)blockIdx.z * sC;
    int m0 = blockIdx.y * BM;
    int n0 = blockIdx.x * BN;
    __shared__ float As[BK][BM + 1];
    __shared__ float Bs[BK][BN + 1];
    int tid = threadIdx.x;
    int tx = tid % 16, ty = tid / 16;
    float acc[4][4] = {};
    for (int kt = 0; kt < K; kt += BK) {
#pragma unroll
        for (int p = 0; p < 4; p++) {
            int idx = p * 256 + tid;
            int ml = idx / BK, kl = idx % BK;
            float v = 0.0f;
            if (m0 + ml < M && kt + kl < K) v = A[(long)(m0 + ml) * lda + kt + kl];
            As[kl][ml] = v;
        }
#pragma unroll
        for (int p = 0; p < 4; p++) {
            int idx = p * 256 + tid;
            int nl = idx / BK, kl = idx % BK;
            float v = 0.0f;
            if (n0 + nl < N && kt + kl < K) v = B[(long)(n0 + nl) * ldb + kt + kl];
            Bs[kl][nl] = v;
        }
        __syncthreads();
#pragma unroll
        for (int k = 0; k < BK; k++) {
            float a[4], b[4];
#pragma unroll
            for (int i = 0; i < 4; i++) a[i] = As[k][ty * 4 + i];
#pragma unroll
            for (int j = 0; j < 4; j++) b[j] = Bs[k][tx * 4 + j];
#pragma unroll
            for (int i = 0; i < 4; i++)
#pragma unroll
                for (int j = 0; j < 4; j++) acc[i][j] = fmaf(a[i], b[j], acc[i][j]);
        }
        __syncthreads();
    }
    float alpha = alpha_const * (alpha_ptr ? *alpha_ptr : 1.0f);
#pragma unroll
    for (int i = 0; i < 4; i++) {
        int m = m0 + ty * 4 + i;
        if (m >= M) continue;
#pragma unroll
        for (int j = 0; j < 4; j++) {
            int n = n0 + tx * 4 + j;
            if (n >= N) continue;
            float v = acc[i][j];
            if (bias) v += bias[n];
            v *= alpha;
            long ci = (long)m * ldc + n;
            C[ci] = (accumulate ? C[ci] : 0.0f) + v;
        }
    }
}

// C[m][n] = sum_k A[m][k]*B[k][n]
__global__ void gemm_nn(const float* __restrict__ A, int lda, long sA,
                        const float* __restrict__ B, int ldb, long sB,
                        float* __restrict__ C, int ldc, long sC,
                        int M, int N, int K) {
    A += (long)blockIdx.z * sA;
    B += (long)blockIdx.z * sB;
    C += (long)blockIdx.z * sC;
    int m0 = blockIdx.y * BM;
    int n0 = blockIdx.x * BN;
    __shared__ float As[BK][BM + 1];
    __shared__ float Bs[BK][BN + 1];
    int tid = threadIdx.x;
    int tx = tid % 16, ty = tid / 16;
    float acc[4][4] = {};
    for (int kt = 0; kt < K; kt += BK) {
#pragma unroll
        for (int p = 0; p < 4; p++) {
            int idx = p * 256 + tid;
            int ml = idx / BK, kl = idx % BK;
            float v = 0.0f;
            if (m0 + ml < M && kt + kl < K) v = A[(long)(m0 + ml) * lda + kt + kl];
            As[kl][ml] = v;
        }
#pragma unroll
        for (int p = 0; p < 4; p++) {
            int idx = p * 256 + tid;
            int kl = idx / BN, nl = idx % BN;
            float v = 0.0f;
            if (kt + kl < K && n0 + nl < N) v = B[(long)(kt + kl) * ldb + n0 + nl];
            Bs[kl][nl] = v;
        }
        __syncthreads();
#pragma unroll
        for (int k = 0; k < BK; k++) {
            float a[4], b[4];
#pragma unroll
            for (int i = 0; i < 4; i++) a[i] = As[k][ty * 4 + i];
#pragma unroll
            for (int j = 0; j < 4; j++) b[j] = Bs[k][tx * 4 + j];
#pragma unroll
            for (int i = 0; i < 4; i++)
#pragma unroll
                for (int j = 0; j < 4; j++) acc[i][j] = fmaf(a[i], b[j], acc[i][j]);
        }
        __syncthreads();
    }
#pragma unroll
    for (int i = 0; i < 4; i++) {
        int m = m0 + ty * 4 + i;
        if (m >= M) continue;
#pragma unroll
        for (int j = 0; j < 4; j++) {
            int n = n0 + tx * 4 + j;
            if (n >= N) continue;
            C[(long)m * ldc + n] = acc[i][j];
        }
    }
}

// ---------------- the big fused z-pass: pair bias + mask + softmax ----------------
// One block per query row i. Reads z[i,:,:] exactly once (537 MB total over grid).
__global__ __launch_bounds__(256) void bias_softmax_kernel(const float* __restrict__ z,
                                                           const float* __restrict__ mask) {
    int i = blockIdx.x;
    int tid = threadIdx.x;  // 256
    __shared__ float sc[NH][S_LEN];          // 32 KB
    __shared__ __align__(16) float sgw[NH * CZ];  // 4 KB
    __shared__ float sgws[NH], sbw[NH];

    for (int idx = tid; idx < NH * CZ; idx += 256) sgw[idx] = g_gw[idx];
    if (tid < NH) { sgws[tid] = g_gwsum[tid]; sbw[tid] = g_bw[tid]; }
    __syncthreads();

    const float4* gw4 = (const float4*)sgw;

    for (int jt = 0; jt < 4; jt++) {
        int j = jt * 256 + tid;
        const float4* zp = (const float4*)(z + ((long)i * S_LEN + j) * CZ);
        float sz = 0.0f, szz = 0.0f;
        float dot[NH] = {0, 0, 0, 0, 0, 0, 0, 0};
#pragma unroll 4
        for (int c = 0; c < 32; c++) {
            float4 zv = zp[c];
            sz += zv.x + zv.y + zv.z + zv.w;
            szz = fmaf(zv.x, zv.x, szz);
            szz = fmaf(zv.y, zv.y, szz);
            szz = fmaf(zv.z, zv.z, szz);
            szz = fmaf(zv.w, zv.w, szz);
#pragma unroll
            for (int h = 0; h < NH; h++) {
                float4 gv = gw4[h * 32 + c];
                dot[h] = fmaf(zv.x, gv.x, dot[h]);
                dot[h] = fmaf(zv.y, gv.y, dot[h]);
                dot[h] = fmaf(zv.z, gv.z, dot[h]);
                dot[h] = fmaf(zv.w, gv.w, dot[h]);
            }
        }
        float mean = sz * (1.0f / CZ);
        float var = szz * (1.0f / CZ) - mean * mean;
        float r = rsqrtf(var + 1e-5f);
        float rm = r * mean;
        float mterm = INFV * (mask[j] - 1.0f);
#pragma unroll
        for (int h = 0; h < NH; h++) {
            float bias = r * dot[h] - rm * sgws[h] + sbw[h];
            float qk = g_scores[((long)h << 20) + (long)i * S_LEN + j];  // already scaled
            sc[h][j] = qk + bias + mterm;
        }
    }
    __syncthreads();

    // softmax: warp w owns head h = w
    int w = tid >> 5, lane = tid & 31;
    float m = -1e30f;
    for (int jj = lane; jj < S_LEN; jj += 32) m = fmaxf(m, sc[w][jj]);
#pragma unroll
    for (int o = 16; o > 0; o >>= 1) m = fmaxf(m, __shfl_xor_sync(0xffffffffu, m, o));
    float ssum = 0.0f;
    for (int jj = lane; jj < S_LEN; jj += 32) {
        float e = __expf(sc[w][jj] - m);
        sc[w][jj] = e;
        ssum += e;
    }
#pragma unroll
    for (int o = 16; o > 0; o >>= 1) ssum += __shfl_xor_sync(0xffffffffu, ssum, o);
    float rinv = 1.0f / ssum;
    float* outp = g_scores + ((long)w << 20) + (long)i * S_LEN;
    for (int jj = lane; jj < S_LEN; jj += 32) outp[jj] = sc[w][jj] * rinv;
}

// ---------------- point branch ----------------
__global__ void vp_kernel() {
    int i = blockIdx.x * blockDim.x + threadIdx.x;
    if (i >= S_LEN) return;
    float4 c = ((const float4*)g_coords)[i];
    const float* row = g_qkvp + (long)i * QKVP_N + 768;
#pragma unroll
    for (int h = 0; h < NH; h++) {
        float sm = 0.0f;
#pragma unroll
        for (int p = 0; p < PV; p++) sm += row[h * PV + p];
        g_vp[i * 24 + h * 3 + 0] = sm * c.x;
        g_vp[i * 24 + h * 3 + 1] = sm * c.y;
        g_vp[i * 24 + h * 3 + 2] = sm * c.z;
    }
}

__global__ __launch_bounds__(256) void point_kernel(const float* __restrict__ mask) {
    int i = blockIdx.x;
    int tid = threadIdx.x;  // 256
    __shared__ float svp[256 * 25];           // padded rows (conflict-free)
    __shared__ float4 sco[256];
    __shared__ float sred[8 * 25];

    float4 ci = ((const float4*)g_coords)[i];
    float mi = mask[i];
    float acc[24] = {};
    float sw = 0.0f;

    for (int jt = 0; jt < 4; jt++) {
        int jbase = jt * 256;
        for (int idx = tid; idx < 256 * 24; idx += 256)
            svp[(idx / 24) * 25 + (idx % 24)] = g_vp[jbase * 24 + idx];
        if (tid < 256) sco[tid] = ((const float4*)g_coords)[jbase + tid];
        __syncthreads();
        int jl = tid;
        float4 cj = sco[jl];
        float dx = ci.x - cj.x, dy = ci.y - cj.y, dz = ci.z - cj.z;
        float dist = sqrtf(dx * dx + dy * dy + dz * dz + 1e-12f);
        float w = __expf(-dist * 0.1f) * mi * mask[jbase + jl];
        sw += w;
#pragma unroll
        for (int p = 0; p < 24; p++) acc[p] = fmaf(w, svp[jl * 25 + p], acc[p]);
        __syncthreads();
    }

    int wr = tid >> 5, lane = tid & 31;
#pragma unroll
    for (int o = 16; o > 0; o >>= 1) {
        sw += __shfl_xor_sync(0xffffffffu, sw, o);
#pragma unroll
        for (int p = 0; p < 24; p++) acc[p] += __shfl_xor_sync(0xffffffffu, acc[p], o);
    }
    if (lane == 0) {
#pragma unroll
        for (int p = 0; p < 24; p++) sred[wr * 25 + p] = acc[p];
        sred[wr * 25 + 24] = sw;
    }
    __syncthreads();
    if (tid < 24) {
        float s = 0.0f, swt = 0.0f;
#pragma unroll
        for (int k = 0; k < 8; k++) { s += sred[k * 25 + tid]; swt += sred[k * 25 + 24]; }
        g_attpts[i * 24 + tid] = s / (swt + 1e-8f);
    }
}

__global__ void copy_kernel(const float* __restrict__ s, float* __restrict__ out, int n) {
    int idx = blockIdx.x * blockDim.x + threadIdx.x;
    for (; idx < n; idx += gridDim.x * blockDim.x) out[idx] = s[idx];
}

// ---------------- launch ----------------
extern "C" void kernel_launch(void* const* d_in, const int* in_sizes, int n_in,
                              void* d_out, int out_size) {
    const float* s       = (const float*)d_in[0];
    const float* z       = (const float*)d_in[1];
    const float* rigids  = (const float*)d_in[2];
    const float* mask    = (const float*)d_in[3];
    const float* ln_s_g  = (const float*)d_in[4];
    const float* ln_s_b  = (const float*)d_in[5];
    const float* ln_z_g  = (const float*)d_in[6];
    const float* ln_z_b  = (const float*)d_in[7];
    const float* Wq      = (const float*)d_in[8];
    const float* Wk      = (const float*)d_in[9];
    const float* Wv      = (const float*)d_in[10];
    const float* W_pair  = (const float*)d_in[11];
    const float* Wo      = (const float*)d_in[12];
    const float* bo      = (const float*)d_in[13];
    const float* Wvp     = (const float*)d_in[14];
    const float* bvp     = (const float*)d_in[15];
    const float* W_po    = (const float*)d_in[16];
    const float* b_po    = (const float*)d_in[17];
    const float* w_scalar= (const float*)d_in[18];
    const float* w_point = (const float*)d_in[19];
    float* out = (float*)d_out;

    // resolve device-global scratch addresses (no allocation, capture-safe)
    float *p_sn, *p_qkvp, *p_scores, *p_ao, *p_Wall, *p_bias832, *p_attpts;
    cudaGetSymbolAddress((void**)&p_sn,      g_sn);
    cudaGetSymbolAddress((void**)&p_qkvp,    g_qkvp);
    cudaGetSymbolAddress((void**)&p_scores,  g_scores);
    cudaGetSymbolAddress((void**)&p_ao,      g_ao);
    cudaGetSymbolAddress((void**)&p_Wall,    g_Wall);
    cudaGetSymbolAddress((void**)&p_bias832, g_bias832);
    cudaGetSymbolAddress((void**)&p_attpts,  g_attpts);

    const float scale = 0.17677669529663687f;  // 1/sqrt(32)

    pack_w_kernel<<<1280, 256>>>(Wq, Wk, Wv, Wvp, bvp);
    prep_pair_kernel<<<1, 128>>>(ln_z_g, ln_z_b, W_pair);
    coords_kernel<<<4, 256>>>(rigids);
    ln_s_kernel<<<S_LEN, 128>>>(s, ln_s_g, ln_s_b);

    // qkvp = s_n @ Wall^T + bias832   (1024 x 832)
    {
        dim3 grid((QKVP_N + BN - 1) / BN, (S_LEN + BM - 1) / BM, 1);
        gemm_nt<<<grid, 256>>>(p_sn, CS, 0, p_Wall, CS, 0, p_qkvp, QKVP_N, 0,
                               S_LEN, QKVP_N, CS, 1.0f, nullptr, p_bias832, 0);
    }
    // qk scores per head: scores[h] = scale * q_h @ k_h^T
    {
        dim3 grid(S_LEN / BN, S_LEN / BM, NH);
        gemm_nt<<<grid, 256>>>(p_qkvp, QKVP_N, 32,
                               p_qkvp + 256, QKVP_N, 32,
                               p_scores, S_LEN, (long)S_LEN * S_LEN,
                               S_LEN, S_LEN, HD, scale, nullptr, nullptr, 0);
    }

    vp_kernel<<<4, 256>>>();
    point_kernel<<<S_LEN, 256>>>(mask);

    // the big fused z pass (bias + mask + softmax, attn in-place)
    bias_softmax_kernel<<<S_LEN, 256>>>(z, mask);

    // ao[:, h*32:(h+1)*32] = attn_h @ v_h
    {
        dim3 grid(1, S_LEN / BM, NH);
        gemm_nn<<<grid, 256>>>(p_scores, S_LEN, (long)S_LEN * S_LEN,
                               p_qkvp + 512, QKVP_N, 32,
                               p_ao, CH, 32,
                               S_LEN, HD, S_LEN);
    }

    // out = s
    copy_kernel<<<512, 256>>>(s, out, S_LEN * CS);
    // out += w_scalar * (ao @ Wo^T + bo)
    {
        dim3 grid((CS + BN - 1) / BN, S_LEN / BM, 1);
        gemm_nt<<<grid, 256>>>(p_ao, CH, 0, Wo, CH, 0, out, CS, 0,
                               S_LEN, CS, CH, 1.0f, w_scalar, bo, 1);
    }
    // out += w_point * (att_pts @ W_po^T + b_po)
    {
        dim3 grid((CS + BN - 1) / BN, S_LEN / BM, 1);
        gemm_nt<<<grid, 256>>>(p_attpts, 24, 0, W_po, 24, 0, out, CS, 0,
                               S_LEN, CS, 24, 1.0f, w_point, b_po, 1);
    }
}

// round 2
// speedup vs baseline: 1.1169x; 1.1169x over previous
#include <cuda_runtime.h>
#include <cuda_bf16.h>
#include <math.h>

#define S_LEN 1024
#define CS 384
#define CZ 128
#define CH 256
#define NH 8
#define HD 32
#define PV 8
#define QKVP_N 832   // 256+256+256+64
#define INFV 100000.0f
#define SC_PITCH 1036  // padded row stride for sc[] (bank-conflict-free head writes)

// ---------------- scratch (__device__ globals, no allocation) ----------------
__device__ __align__(16) float g_sn[S_LEN * CS];
__device__ __align__(16) float g_qkvp[S_LEN * QKVP_N];
__device__ __align__(16) float g_scores[S_LEN * NH * S_LEN];   // layout [i][h][j]
__device__ __align__(16) float g_ao[S_LEN * CH];
__device__ __align__(16) float g_aop[4 * S_LEN * CH];          // split-K partials
__device__ __align__(16) float g_Wall[QKVP_N * CS];
__device__ __align__(16) float g_bias832[QKVP_N];
__device__ __align__(16) float g_gw[NH * CZ];
__device__ float g_gwsum[NH];
__device__ float g_bw[NH];
__device__ __align__(16) float g_coords[S_LEN * 4];
__device__ __align__(16) float g_vp[S_LEN * 24];
__device__ __align__(16) float g_attpts[S_LEN * 24];

// ---------------- packed f32x2 helpers (sm_103a FFMA2) ----------------
__device__ __forceinline__ unsigned long long pk(float x, float y) {
    float2 v = make_float2(x, y);
    return *reinterpret_cast<unsigned long long*>(&v);
}
__device__ __forceinline__ float2 upk(unsigned long long u) {
    return *reinterpret_cast<float2*>(&u);
}
__device__ __forceinline__ unsigned long long fma2(unsigned long long a,
                                                   unsigned long long b,
                                                   unsigned long long c) {
    unsigned long long d;
    asm("fma.rn.f32x2 %0, %1, %2, %3;" : "=l"(d) : "l"(a), "l"(b), "l"(c));
    return d;
}
__device__ __forceinline__ unsigned long long add2(unsigned long long a,
                                                   unsigned long long b) {
    unsigned long long d;
    asm("add.rn.f32x2 %0, %1, %2;" : "=l"(d) : "l"(a), "l"(b));
    return d;
}

// ---------------- prep kernels ----------------
__global__ void pack_w_kernel(const float* __restrict__ Wq, const float* __restrict__ Wk,
                              const float* __restrict__ Wv, const float* __restrict__ Wvp,
                              const float* __restrict__ bvp) {
    int idx = blockIdx.x * blockDim.x + threadIdx.x;
    int total = QKVP_N * CS;
    for (; idx < total; idx += gridDim.x * blockDim.x) {
        int r = idx / CS, c = idx % CS;
        float v;
        if (r < 256)      v = Wq[r * CS + c];
        else if (r < 512) v = Wk[(r - 256) * CS + c];
        else if (r < 768) v = Wv[(r - 512) * CS + c];
        else              v = Wvp[(r - 768) * CS + c];
        g_Wall[idx] = v;
    }
    int t = blockIdx.x * blockDim.x + threadIdx.x;
    if (t < QKVP_N) g_bias832[t] = (t >= 768) ? bvp[t - 768] : 0.0f;
}

__global__ void prep_pair_kernel(const float* __restrict__ ln_z_g,
                                 const float* __restrict__ ln_z_b,
                                 const float* __restrict__ W_pair) {
    __shared__ float red[CZ];
    int c = threadIdx.x;  // 128
    for (int h = 0; h < NH; h++) {
        float w = W_pair[h * CZ + c];
        float gv = ln_z_g[c] * w;
        g_gw[h * CZ + c] = gv;
        red[c] = gv; __syncthreads();
        for (int s = 64; s > 0; s >>= 1) { if (c < s) red[c] += red[c + s]; __syncthreads(); }
        if (c == 0) g_gwsum[h] = red[0];
        __syncthreads();
        red[c] = ln_z_b[c] * w; __syncthreads();
        for (int s = 64; s > 0; s >>= 1) { if (c < s) red[c] += red[c + s]; __syncthreads(); }
        if (c == 0) g_bw[h] = red[0];
        __syncthreads();
    }
}

__global__ void coords_kernel(const float* __restrict__ rigids) {
    int i = blockIdx.x * blockDim.x + threadIdx.x;
    if (i < S_LEN) {
        const float* rg = rigids + i * 16;
        float4 c;
        c.x = rg[3]; c.y = rg[7]; c.z = rg[11]; c.w = 0.0f;
        ((float4*)g_coords)[i] = c;
    }
}

__global__ void ln_s_kernel(const float* __restrict__ s, const float* __restrict__ g,
                            const float* __restrict__ b) {
    int i = blockIdx.x;
    const float* row = s + (long)i * CS;
    __shared__ float red[128];
    int t = threadIdx.x;  // 128
    float x0 = row[t], x1 = row[t + 128], x2 = row[t + 256];
    red[t] = x0 + x1 + x2; __syncthreads();
    for (int st = 64; st > 0; st >>= 1) { if (t < st) red[t] += red[t + st]; __syncthreads(); }
    float mean = red[0] * (1.0f / CS);
    __syncthreads();
    float d0 = x0 - mean, d1 = x1 - mean, d2 = x2 - mean;
    red[t] = d0 * d0 + d1 * d1 + d2 * d2; __syncthreads();
    for (int st = 64; st > 0; st >>= 1) { if (t < st) red[t] += red[t + st]; __syncthreads(); }
    float r = rsqrtf(red[0] * (1.0f / CS) + 1e-5f);
    float* o = g_sn + (long)i * CS;
    o[t]       = d0 * r * g[t]       + b[t];
    o[t + 128] = d1 * r * g[t + 128] + b[t + 128];
    o[t + 256] = d2 * r * g[t + 256] + b[t + 256];
}

// ---------------- generic tiled GEMM (A row-major, B^T row-major) ----------------
#define BM 64
#define BN 64
#define BK 16

// C[m][n] = base + alpha * ( sum_k A[m][k]*B[n][k] + bias[n] )
// base = initC[m*ldc+n] if initC, else (accumulate ? C[..] : 0)
__global__ void gemm_nt(const float* __restrict__ A, int lda, long sA,
                        const float* __restrict__ B, int ldb, long sB,
                        float* __restrict__ C, int ldc, long sC,
                        int M, int N, int K,
                        float alpha_const, const float* alpha_ptr,
                        const float* __restrict__ bias, int accumulate,
                        const float* __restrict__ initC) {
    A += (long)blockIdx.z * sA;
    B += (long)blockIdx.z * sB;
    C += (long)blockIdx.z * sC;
    int m0 = blockIdx.y * BM;
    int n0 = blockIdx.x * BN;
    __shared__ float As[BK][BM + 1];
    __shared__ float Bs[BK][BN + 1];
    int tid = threadIdx.x;
    int tx = tid % 16, ty = tid / 16;
    float acc[4][4] = {};
    for (int kt = 0; kt < K; kt += BK) {
#pragma unroll
        for (int p = 0; p < 4; p++) {
            int idx = p * 256 + tid;
            int ml = idx / BK, kl = idx % BK;
            float v = 0.0f;
            if (m0 + ml < M && kt + kl < K) v = A[(long)(m0 + ml) * lda + kt + kl];
            As[kl][ml] = v;
        }
#pragma unroll
        for (int p = 0; p < 4; p++) {
            int idx = p * 256 + tid;
            int nl = idx / BK, kl = idx % BK;
            float v = 0.0f;
            if (n0 + nl < N && kt + kl < K) v = B[(long)(n0 + nl) * ldb + kt + kl];
            Bs[kl][nl] = v;
        }
        __syncthreads();
#pragma unroll
        for (int k = 0; k < BK; k++) {
            float a[4], b[4];
#pragma unroll
            for (int i = 0; i < 4; i++) a[i] = As[k][ty * 4 + i];
#pragma unroll
            for (int j = 0; j < 4; j++) b[j] = Bs[k][tx * 4 + j];
#pragma unroll
            for (int i = 0; i < 4; i++)
#pragma unroll
                for (int j = 0; j < 4; j++) acc[i][j] = fmaf(a[i], b[j], acc[i][j]);
        }
        __syncthreads();
    }
    float alpha = alpha_const * (alpha_ptr ? *alpha_ptr : 1.0f);
#pragma unroll
    for (int i = 0; i < 4; i++) {
        int m = m0 + ty * 4 + i;
        if (m >= M) continue;
#pragma unroll
        for (int j = 0; j < 4; j++) {
            int n = n0 + tx * 4 + j;
            if (n >= N) continue;
            float v = acc[i][j];
            if (bias) v += bias[n];
            v *= alpha;
            long ci = (long)m * ldc + n;
            float base = initC ? initC[ci] : (accumulate ? C[ci] : 0.0f);
            C[ci] = base + v;
        }
    }
}

// ---------------- split-K attn @ v ----------------
// grid (4 ksplit, 16 mtile, 8 head), block 256. Out: g_aop[ks][i][h*32+c]
__global__ __launch_bounds__(256) void attnv_kernel() {
    int ks = blockIdx.x;
    int m0 = blockIdx.y * 64;
    int h  = blockIdx.z;
    const float* A = g_scores + (long)h * S_LEN;        // attn[i][h][k], row stride 8192
    const float* B = g_qkvp + 512 + h * 32;             // v[k][n], row stride 832
    float* C = g_aop + (long)ks * (S_LEN * CH);
    __shared__ float As[16][65];
    __shared__ float Bs[16][33];
    int tid = threadIdx.x;
    int tx = tid % 16, ty = tid / 16;   // tx: 2 cols, ty: 4 rows
    float acc[4][2] = {};
    int k0 = ks * 256;
    for (int kt = 0; kt < 256; kt += 16) {
#pragma unroll
        for (int p = 0; p < 4; p++) {
            int idx = p * 256 + tid;
            int ml = idx / 16, kl = idx % 16;
            As[kl][ml] = A[(long)(m0 + ml) * (NH * S_LEN) + k0 + kt + kl];
        }
#pragma unroll
        for (int p = 0; p < 2; p++) {
            int idx = p * 256 + tid;
            int kl = idx / 32, nl = idx % 32;
            Bs[kl][nl] = B[(long)(k0 + kt + kl) * QKVP_N + nl];
        }
        __syncthreads();
#pragma unroll
        for (int k = 0; k < 16; k++) {
            float a[4], b[2];
#pragma unroll
            for (int i = 0; i < 4; i++) a[i] = As[k][ty * 4 + i];
#pragma unroll
            for (int j = 0; j < 2; j++) b[j] = Bs[k][tx * 2 + j];
#pragma unroll
            for (int i = 0; i < 4; i++)
#pragma unroll
                for (int j = 0; j < 2; j++) acc[i][j] = fmaf(a[i], b[j], acc[i][j]);
        }
        __syncthreads();
    }
#pragma unroll
    for (int i = 0; i < 4; i++)
#pragma unroll
        for (int j = 0; j < 2; j++)
            C[(long)(m0 + ty * 4 + i) * CH + h * 32 + tx * 2 + j] = acc[i][j];
}

__global__ void combine_ao_kernel() {
    int idx = blockIdx.x * blockDim.x + threadIdx.x;
    if (idx < S_LEN * CH)
        g_ao[idx] = g_aop[idx] + g_aop[S_LEN * CH + idx] +
                    g_aop[2 * S_LEN * CH + idx] + g_aop[3 * S_LEN * CH + idx];
}

// ---------------- fused z-pass: pair bias + mask + softmax (coalesced) ----------------
// Block = query row i. Warp processes 2 j-rows per iteration: 16 lanes per row,
// each lane owns 8 channels (4 at c0=r16*4, 4 at c1=64+r16*4); head weights in regs.
__global__ __launch_bounds__(256, 2) void bias_softmax_kernel(const float* __restrict__ z,
                                                              const float* __restrict__ mask) {
    int i = blockIdx.x;
    int tid = threadIdx.x;  // 256
    int w = tid >> 5, lane = tid & 31;
    int sub = lane >> 4, r16 = lane & 15;

    __shared__ float sc[NH * SC_PITCH];   // ~33 KB, padded rows
    __shared__ float sgws[NH], sbw[NH];

    // init sc = qk + mask term (coalesced 32KB read)
    const float* qk = g_scores + (long)i * (NH * S_LEN);
    for (int idx = tid; idx < NH * S_LEN; idx += 256) {
        int j = idx & (S_LEN - 1);
        int h = idx >> 10;
        sc[h * SC_PITCH + j] = qk[idx] + INFV * (mask[j] - 1.0f);
    }
    if (tid < NH) { sgws[tid] = g_gwsum[tid]; sbw[tid] = g_bw[tid]; }

    // per-lane head weights in registers: 8 heads x 8 channels (as f32x2 pairs)
    int c0 = r16 * 4, c1 = 64 + r16 * 4;
    unsigned long long wa01[NH], wa23[NH], wc01[NH], wc23[NH];
#pragma unroll
    for (int h = 0; h < NH; h++) {
        float4 wa = *(const float4*)(g_gw + h * CZ + c0);
        float4 wc = *(const float4*)(g_gw + h * CZ + c1);
        wa01[h] = pk(wa.x, wa.y); wa23[h] = pk(wa.z, wa.w);
        wc01[h] = pk(wc.x, wc.y); wc23[h] = pk(wc.z, wc.w);
    }
    __syncthreads();

    const unsigned long long ZERO = 0ull;

    for (int p = w; p < S_LEN / 2; p += 8) {
        int j = p * 2 + sub;
        const float4* zp = (const float4*)(z + ((long)i * S_LEN + j) * CZ);
        float4 z0 = zp[r16];        // channels c0..c0+3 (first 256B of row)
        float4 z1 = zp[16 + r16];   // channels c1..c1+3 (second 256B)
        unsigned long long za01 = pk(z0.x, z0.y), za23 = pk(z0.z, z0.w);
        unsigned long long zc01 = pk(z1.x, z1.y), zc23 = pk(z1.z, z1.w);

        // sums
        float2 s2 = upk(add2(add2(za01, za23), add2(zc01, zc23)));
        float sz = s2.x + s2.y;
        float2 q2 = upk(fma2(za01, za01, fma2(za23, za23,
                        fma2(zc01, zc01, fma2(zc23, zc23, ZERO)))));
        float szz = q2.x + q2.y;

        // 8-head dots (packed FFMA2)
        float dot[NH];
#pragma unroll
        for (int h = 0; h < NH; h++) {
            float2 a = upk(fma2(za01, wa01[h], fma2(za23, wa23[h],
                           fma2(zc01, wc01[h], fma2(zc23, wc23[h], ZERO)))));
            dot[h] = a.x + a.y;
        }

        // reduce across the 16 lanes of this sub-row
#pragma unroll
        for (int o = 8; o > 0; o >>= 1) {
            sz  += __shfl_xor_sync(0xffffffffu, sz, o);
            szz += __shfl_xor_sync(0xffffffffu, szz, o);
#pragma unroll
            for (int h = 0; h < NH; h++)
                dot[h] += __shfl_xor_sync(0xffffffffu, dot[h], o);
        }

        float mean = sz * (1.0f / CZ);
        float var = szz * (1.0f / CZ) - mean * mean;
        float r = rsqrtf(var + 1e-5f);
        float rm = r * mean;
        if (r16 < NH) {
            int h = r16;
            sc[h * SC_PITCH + j] += r * dot[h] - rm * sgws[h] + sbw[h];
        }
    }
    __syncthreads();

    // softmax: warp w owns head h = w
    float m = -1e30f;
    const float* srow = sc + w * SC_PITCH;
    for (int jj = lane; jj < S_LEN; jj += 32) m = fmaxf(m, srow[jj]);
#pragma unroll
    for (int o = 16; o > 0; o >>= 1) m = fmaxf(m, __shfl_xor_sync(0xffffffffu, m, o));
    float ssum = 0.0f;
    float* srw = sc + w * SC_PITCH;
    for (int jj = lane; jj < S_LEN; jj += 32) {
        float e = __expf(srw[jj] - m);
        srw[jj] = e;
        ssum += e;
    }
#pragma unroll
    for (int o = 16; o > 0; o >>= 1) ssum += __shfl_xor_sync(0xffffffffu, ssum, o);
    float rinv = 1.0f / ssum;
    float* outp = g_scores + (long)i * (NH * S_LEN) + (long)w * S_LEN;
    for (int jj = lane; jj < S_LEN; jj += 32) outp[jj] = srw[jj] * rinv;
}

// ---------------- point branch ----------------
__global__ void vp_kernel() {
    int i = blockIdx.x * blockDim.x + threadIdx.x;
    if (i >= S_LEN) return;
    float4 c = ((const float4*)g_coords)[i];
    const float* row = g_qkvp + (long)i * QKVP_N + 768;
#pragma unroll
    for (int h = 0; h < NH; h++) {
        float sm = 0.0f;
#pragma unroll
        for (int p = 0; p < PV; p++) sm += row[h * PV + p];
        g_vp[i * 24 + h * 3 + 0] = sm * c.x;
        g_vp[i * 24 + h * 3 + 1] = sm * c.y;
        g_vp[i * 24 + h * 3 + 2] = sm * c.z;
    }
}

__global__ __launch_bounds__(256) void point_kernel(const float* __restrict__ mask) {
    int i = blockIdx.x;
    int tid = threadIdx.x;  // 256
    __shared__ float svp[256 * 25];
    __shared__ float4 sco[256];
    __shared__ float sred[8 * 25];

    float4 ci = ((const float4*)g_coords)[i];
    float mi = mask[i];
    float acc[24] = {};
    float sw = 0.0f;

    for (int jt = 0; jt < 4; jt++) {
        int jbase = jt * 256;
        for (int idx = tid; idx < 256 * 24; idx += 256)
            svp[(idx / 24) * 25 + (idx % 24)] = g_vp[jbase * 24 + idx];
        sco[tid] = ((const float4*)g_coords)[jbase + tid];
        __syncthreads();
        int jl = tid;
        float4 cj = sco[jl];
        float dx = ci.x - cj.x, dy = ci.y - cj.y, dz = ci.z - cj.z;
        float dist = sqrtf(dx * dx + dy * dy + dz * dz + 1e-12f);
        float wgt = __expf(-dist * 0.1f) * mi * mask[jbase + jl];
        sw += wgt;
#pragma unroll
        for (int p = 0; p < 24; p++) acc[p] = fmaf(wgt, svp[jl * 25 + p], acc[p]);
        __syncthreads();
    }

    int wr = tid >> 5, lane = tid & 31;
#pragma unroll
    for (int o = 16; o > 0; o >>= 1) {
        sw += __shfl_xor_sync(0xffffffffu, sw, o);
#pragma unroll
        for (int p = 0; p < 24; p++) acc[p] += __shfl_xor_sync(0xffffffffu, acc[p], o);
    }
    if (lane == 0) {
#pragma unroll
        for (int p = 0; p < 24; p++) sred[wr * 25 + p] = acc[p];
        sred[wr * 25 + 24] = sw;
    }
    __syncthreads();
    if (tid < 24) {
        float s = 0.0f, swt = 0.0f;
#pragma unroll
        for (int k = 0; k < 8; k++) { s += sred[k * 25 + tid]; swt += sred[k * 25 + 24]; }
        g_attpts[i * 24 + tid] = s / (swt + 1e-8f);
    }
}

// ---------------- launch ----------------
extern "C" void kernel_launch(void* const* d_in, const int* in_sizes, int n_in,
                              void* d_out, int out_size) {
    const float* s       = (const float*)d_in[0];
    const float* z       = (const float*)d_in[1];
    const float* rigids  = (const float*)d_in[2];
    const float* mask    = (const float*)d_in[3];
    const float* ln_s_g  = (const float*)d_in[4];
    const float* ln_s_b  = (const float*)d_in[5];
    const float* ln_z_g  = (const float*)d_in[6];
    const float* ln_z_b  = (const float*)d_in[7];
    const float* Wq      = (const float*)d_in[8];
    const float* Wk      = (const float*)d_in[9];
    const float* Wv      = (const float*)d_in[10];
    const float* W_pair  = (const float*)d_in[11];
    const float* Wo      = (const float*)d_in[12];
    const float* bo      = (const float*)d_in[13];
    const float* Wvp     = (const float*)d_in[14];
    const float* bvp     = (const float*)d_in[15];
    const float* W_po    = (const float*)d_in[16];
    const float* b_po    = (const float*)d_in[17];
    const float* w_scalar= (const float*)d_in[18];
    const float* w_point = (const float*)d_in[19];
    float* out = (float*)d_out;

    float *p_sn, *p_qkvp, *p_scores, *p_ao, *p_Wall, *p_bias832, *p_attpts;
    cudaGetSymbolAddress((void**)&p_sn,      g_sn);
    cudaGetSymbolAddress((void**)&p_qkvp,    g_qkvp);
    cudaGetSymbolAddress((void**)&p_scores,  g_scores);
    cudaGetSymbolAddress((void**)&p_ao,      g_ao);
    cudaGetSymbolAddress((void**)&p_Wall,    g_Wall);
    cudaGetSymbolAddress((void**)&p_bias832, g_bias832);
    cudaGetSymbolAddress((void**)&p_attpts,  g_attpts);

    const float scale = 0.17677669529663687f;  // 1/sqrt(32)

    pack_w_kernel<<<1280, 256>>>(Wq, Wk, Wv, Wvp, bvp);
    prep_pair_kernel<<<1, 128>>>(ln_z_g, ln_z_b, W_pair);
    coords_kernel<<<4, 256>>>(rigids);
    ln_s_kernel<<<S_LEN, 128>>>(s, ln_s_g, ln_s_b);

    // qkvp = s_n @ Wall^T + bias832   (1024 x 832)
    {
        dim3 grid((QKVP_N + BN - 1) / BN, (S_LEN + BM - 1) / BM, 1);
        gemm_nt<<<grid, 256>>>(p_sn, CS, 0, p_Wall, CS, 0, p_qkvp, QKVP_N, 0,
                               S_LEN, QKVP_N, CS, 1.0f, nullptr, p_bias832, 0, nullptr);
    }
    // qk scores per head (layout [i][h][j]): scores = scale * q_h @ k_h^T
    {
        dim3 grid(S_LEN / BN, S_LEN / BM, NH);
        gemm_nt<<<grid, 256>>>(p_qkvp, QKVP_N, 32,
                               p_qkvp + 256, QKVP_N, 32,
                               p_scores, NH * S_LEN, S_LEN,
                               S_LEN, S_LEN, HD, scale, nullptr, nullptr, 0, nullptr);
    }

    vp_kernel<<<4, 256>>>();
    point_kernel<<<S_LEN, 256>>>(mask);

    // the big fused z pass (bias + mask + softmax, attn in-place)
    bias_softmax_kernel<<<S_LEN, 256>>>(z, mask);

    // split-K attn @ v, then combine
    {
        dim3 grid(4, S_LEN / 64, NH);
        attnv_kernel<<<grid, 256>>>();
        combine_ao_kernel<<<(S_LEN * CH + 255) / 256, 256>>>();
    }

    // out = s + w_scalar * (ao @ Wo^T + bo)
    {
        dim3 grid((CS + BN - 1) / BN, S_LEN / BM, 1);
        gemm_nt<<<grid, 256>>>(p_ao, CH, 0, Wo, CH, 0, out, CS, 0,
                               S_LEN, CS, CH, 1.0f, w_scalar, bo, 0, s);
    }
    // out += w_point * (att_pts @ W_po^T + b_po)
    {
        dim3 grid((CS + BN - 1) / BN, S_LEN / BM, 1);
        gemm_nt<<<grid, 256>>>(p_attpts, 24, 0, W_po, 24, 0, out, CS, 0,
                               S_LEN, CS, 24, 1.0f, w_point, b_po, 1, nullptr);
    }
}